// round 1
// baseline (speedup 1.0000x reference)
#include <cuda_runtime.h>
#include <cuda_bf16.h>
#include <cstddef>

#define B_ 4096
#define T_ 80
#define V_ 10000
#define E_ 100
#define U_ 1024

#define MT 128
#define NT 128
#define KC 16
#define AS_STRIDE (2*MT + 4)   // 260 floats; *4 = 1040 B, multiple of 16 for LDS.128

// Ping-pong hidden state buffers (allocation-free scratch).
__device__ float g_h[2][(size_t)B_ * U_];

__device__ __forceinline__ unsigned long long ffma2(unsigned long long a,
                                                    unsigned long long b,
                                                    unsigned long long c) {
    unsigned long long d;
    asm("fma.rn.f32x2 %0, %1, %2, %3;" : "=l"(d) : "l"(a), "l"(b), "l"(c));
    return d;
}

__global__ void zero_h_kernel() {
    size_t i = (size_t)blockIdx.x * blockDim.x + threadIdx.x;
    if (i < (size_t)B_ * U_) g_h[0][i] = 0.0f;
}

// One recurrence step: h_new = tanh( x_t @ Wx + b + h_prev @ Wh )
// x_t gathered on the fly from emb via inputs[:, t].
// Grid: (U_/NT, B_/MT) = (8, 32). Block: 256 threads.
__global__ __launch_bounds__(256, 2)
void rnn_step_kernel(const int*   __restrict__ inputs,
                     const float* __restrict__ emb,
                     const float* __restrict__ Wx,
                     const float* __restrict__ Wh,
                     const float* __restrict__ bvec,
                     int t)
{
    __shared__ float sA[KC][AS_STRIDE];   // A tile, each value duplicated (a,a)
    __shared__ float sB[KC][NT];
    __shared__ int   sIdx[MT];

    const int tid = threadIdx.x;
    const int n0 = blockIdx.x * NT;
    const int m0 = blockIdx.y * MT;

    const float* __restrict__ hprev = g_h[t & 1];
    float*       __restrict__ hnew  = g_h[(t & 1) ^ 1];

    if (tid < MT) sIdx[tid] = inputs[(size_t)(m0 + tid) * T_ + t];

    const int tx  = tid & 15;        // 0..15 : column group
    const int ty  = tid >> 4;        // 0..15 : row group
    const int li  = tid >> 1;        // 0..127: A-load row
    const int lkb = (tid & 1) * 8;   // 0 or 8: A-load k base within chunk
    const int bkk = tid >> 4;        // 0..15 : B-load kk
    const int bj  = (tid & 15) * 8;  // B-load col base

    unsigned long long acc[8][4];
#pragma unroll
    for (int i = 0; i < 8; i++)
#pragma unroll
        for (int j = 0; j < 4; j++) acc[i][j] = 0ull;

    // ---------------- Wh phase: K = 1024 ----------------
    for (int k0 = 0; k0 < U_; k0 += KC) {
        __syncthreads();
        {
            const float4* src = (const float4*)(hprev + (size_t)(m0 + li) * U_ + k0 + lkb);
            float4 v0 = src[0];
            float4 v1 = src[1];
            *(float2*)&sA[lkb + 0][2 * li] = make_float2(v0.x, v0.x);
            *(float2*)&sA[lkb + 1][2 * li] = make_float2(v0.y, v0.y);
            *(float2*)&sA[lkb + 2][2 * li] = make_float2(v0.z, v0.z);
            *(float2*)&sA[lkb + 3][2 * li] = make_float2(v0.w, v0.w);
            *(float2*)&sA[lkb + 4][2 * li] = make_float2(v1.x, v1.x);
            *(float2*)&sA[lkb + 5][2 * li] = make_float2(v1.y, v1.y);
            *(float2*)&sA[lkb + 6][2 * li] = make_float2(v1.z, v1.z);
            *(float2*)&sA[lkb + 7][2 * li] = make_float2(v1.w, v1.w);

            const float4* bs = (const float4*)(Wh + (size_t)(k0 + bkk) * U_ + n0 + bj);
            *(float4*)&sB[bkk][bj]     = bs[0];
            *(float4*)&sB[bkk][bj + 4] = bs[1];
        }
        __syncthreads();
#pragma unroll
        for (int kk = 0; kk < KC; kk++) {
            ulonglong2 a01 = *(ulonglong2*)&sA[kk][8 * ty];
            ulonglong2 a23 = *(ulonglong2*)&sA[kk][8 * ty + 4];
            ulonglong2 a45 = *(ulonglong2*)&sA[kk][128 + 8 * ty];
            ulonglong2 a67 = *(ulonglong2*)&sA[kk][128 + 8 * ty + 4];
            ulonglong2 b01 = *(ulonglong2*)&sB[kk][4 * tx];
            ulonglong2 b23 = *(ulonglong2*)&sB[kk][4 * tx + 64];
            unsigned long long av[8] = {a01.x, a01.y, a23.x, a23.y,
                                        a45.x, a45.y, a67.x, a67.y};
            unsigned long long bv[4] = {b01.x, b01.y, b23.x, b23.y};
#pragma unroll
            for (int i = 0; i < 8; i++)
#pragma unroll
                for (int j = 0; j < 4; j++)
                    acc[i][j] = ffma2(av[i], bv[j], acc[i][j]);
        }
    }

    // ---------------- Wx phase: K = 100 (embedding gather) ----------------
    for (int k0 = 0; k0 < E_; k0 += KC) {
        __syncthreads();
        {
            const float* er = emb + (size_t)sIdx[li] * E_;
#pragma unroll
            for (int q = 0; q < 8; q++) {
                int k = k0 + lkb + q;
                float v = (k < E_) ? er[k] : 0.0f;
                *(float2*)&sA[lkb + q][2 * li] = make_float2(v, v);
            }
            int kb = k0 + bkk;
            if (kb < E_) {
                const float4* bs = (const float4*)(Wx + (size_t)kb * U_ + n0 + bj);
                *(float4*)&sB[bkk][bj]     = bs[0];
                *(float4*)&sB[bkk][bj + 4] = bs[1];
            } else {
                float4 z = make_float4(0.f, 0.f, 0.f, 0.f);
                *(float4*)&sB[bkk][bj]     = z;
                *(float4*)&sB[bkk][bj + 4] = z;
            }
        }
        __syncthreads();
#pragma unroll
        for (int kk = 0; kk < KC; kk++) {
            ulonglong2 a01 = *(ulonglong2*)&sA[kk][8 * ty];
            ulonglong2 a23 = *(ulonglong2*)&sA[kk][8 * ty + 4];
            ulonglong2 a45 = *(ulonglong2*)&sA[kk][128 + 8 * ty];
            ulonglong2 a67 = *(ulonglong2*)&sA[kk][128 + 8 * ty + 4];
            ulonglong2 b01 = *(ulonglong2*)&sB[kk][4 * tx];
            ulonglong2 b23 = *(ulonglong2*)&sB[kk][4 * tx + 64];
            unsigned long long av[8] = {a01.x, a01.y, a23.x, a23.y,
                                        a45.x, a45.y, a67.x, a67.y};
            unsigned long long bv[4] = {b01.x, b01.y, b23.x, b23.y};
#pragma unroll
            for (int i = 0; i < 8; i++)
#pragma unroll
                for (int j = 0; j < 4; j++)
                    acc[i][j] = ffma2(av[i], bv[j], acc[i][j]);
        }
    }

    // ---------------- Epilogue: bias + tanh + store ----------------
#pragma unroll
    for (int i = 0; i < 8; i++) {
        int r = m0 + ((i < 4) ? (ty * 4 + i) : (64 + ty * 4 + (i - 4)));
#pragma unroll
        for (int j = 0; j < 4; j++) {
            int c = n0 + ((j < 2) ? (4 * tx + 2 * j) : (64 + 4 * tx + 2 * (j - 2)));
            float lo, hi;
            asm("mov.b64 {%0, %1}, %2;" : "=f"(lo), "=f"(hi) : "l"(acc[i][j]));
            float z0 = tanhf(lo + bvec[c]);
            float z1 = tanhf(hi + bvec[c + 1]);
            *(float2*)&hnew[(size_t)r * U_ + c] = make_float2(z0, z1);
        }
    }
}

// out[row] = h_last[row, :] @ Wo + bo
__global__ void final_proj_kernel(const float* __restrict__ Wo,
                                  const float* __restrict__ bo,
                                  float* __restrict__ out)
{
    const float* h = g_h[0];   // after t = 79, result lives in buffer 0
    int row = blockIdx.x;
    int tid = threadIdx.x;     // 128 threads
    float s = 0.0f;
    const float* hr = h + (size_t)row * U_;
#pragma unroll
    for (int i = tid; i < U_; i += 128) s += hr[i] * Wo[i];
#pragma unroll
    for (int o = 16; o > 0; o >>= 1) s += __shfl_down_sync(0xffffffffu, s, o);
    __shared__ float red[4];
    if ((tid & 31) == 0) red[tid >> 5] = s;
    __syncthreads();
    if (tid == 0) out[row] = red[0] + red[1] + red[2] + red[3] + bo[0];
}

extern "C" void kernel_launch(void* const* d_in, const int* in_sizes, int n_in,
                              void* d_out, int out_size)
{
    const int*   inputs = (const int*)  d_in[0];
    const float* emb    = (const float*)d_in[1];
    const float* Wx     = (const float*)d_in[2];
    const float* Wh     = (const float*)d_in[3];
    const float* b      = (const float*)d_in[4];
    const float* Wo     = (const float*)d_in[5];
    const float* bo     = (const float*)d_in[6];
    float* out = (float*)d_out;

    // h0 = 0
    {
        size_t n = (size_t)B_ * U_;
        int threads = 256;
        int blocks = (int)((n + threads - 1) / threads);
        zero_h_kernel<<<blocks, threads>>>();
    }

    // 80 recurrence steps (ping-pong between g_h[0] and g_h[1])
    dim3 grid(U_ / NT, B_ / MT);
    for (int t = 0; t < T_; t++) {
        rnn_step_kernel<<<grid, 256>>>(inputs, emb, Wx, Wh, b, t);
    }

    // Final projection: [B, 1]
    final_proj_kernel<<<B_, 128>>>(Wo, bo, out);
}

// round 6
// speedup vs baseline: 2.5576x; 2.5576x over previous
#include <cuda_runtime.h>
#include <cuda_bf16.h>
#include <mma.h>
#include <cstdint>
#include <cstddef>

using namespace nvcuda;

#define B_ 4096
#define T_ 80
#define V_ 10000
#define E_ 100
#define U_ 1024

#define KTOT 1152            // 1024 (Wh) + 128 (Wx padded from 100)
#define EPAD 128             // padded embedding width
#define NCHUNK 36            // KTOT / 32
#define MT 256
#define NT 128
#define KC 32
#define NSTAGE 3
#define LDAB 40              // leading dim in bf16 elements (80 B, multiple of 16 B)

// byte sizes
#define A_PLANE_B (MT * LDAB * 2)        // 20480
#define A_STAGE_B (2 * A_PLANE_B)        // 40960 (hi + lo)
#define B_PLANE_B (NT * LDAB * 2)        // 10240
#define B_STAGE_B (2 * B_PLANE_B)        // 20480
#define SM_A_OFF   0
#define SM_B_OFF   (NSTAGE * A_STAGE_B)                 // 122880
#define SM_SCR_OFF (SM_B_OFF + NSTAGE * B_STAGE_B)      // 184320
#define SM_IDX_OFF (SM_SCR_OFF + 8 * 16 * 24 * 4)       // 196608
#define SMEM_TOTAL (SM_IDX_OFF + MT * 4)                // 197632

// ---- device scratch (allocation-free) ----
__device__ __align__(256) __nv_bfloat16 g_h_hi[2][(size_t)B_ * U_];
__device__ __align__(256) __nv_bfloat16 g_h_lo[2][(size_t)B_ * U_];
__device__ __align__(256) __nv_bfloat16 g_Bth[(size_t)U_ * KTOT];   // [n][k] hi
__device__ __align__(256) __nv_bfloat16 g_Btl[(size_t)U_ * KTOT];   // [n][k] lo
__device__ __align__(256) __nv_bfloat16 g_emb_hi[(size_t)V_ * EPAD];
__device__ __align__(256) __nv_bfloat16 g_emb_lo[(size_t)V_ * EPAD];

static __device__ __forceinline__ uint32_t smem_u32(const void* p) {
    uint32_t a;
    asm("{ .reg .u64 t; cvta.to.shared.u64 t, %1; cvt.u32.u64 %0, t; }" : "=r"(a) : "l"(p));
    return a;
}
static __device__ __forceinline__ void cp_async16(uint32_t s, const void* g) {
    asm volatile("cp.async.cg.shared.global [%0], [%1], 16;" :: "r"(s), "l"(g));
}
static __device__ __forceinline__ void split_bf16(float v, __nv_bfloat16& hi, __nv_bfloat16& lo) {
    hi = __float2bfloat16(v);
    lo = __float2bfloat16(v - __bfloat162float(hi));
}

// ---------------- prep kernels ----------------
__global__ void prep_bt_kernel(const float* __restrict__ Wh, const float* __restrict__ Wx) {
    int idx = blockIdx.x * 256 + threadIdx.x;
    if (idx >= U_ * KTOT) return;
    int n = idx / KTOT;
    int k = idx - n * KTOT;
    float v = 0.0f;
    if (k < U_)            v = Wh[(size_t)k * U_ + n];
    else if (k < U_ + E_)  v = Wx[(size_t)(k - U_) * U_ + n];
    __nv_bfloat16 hi, lo; split_bf16(v, hi, lo);
    g_Bth[idx] = hi; g_Btl[idx] = lo;
}
__global__ void prep_emb_kernel(const float* __restrict__ emb) {
    int idx = blockIdx.x * 256 + threadIdx.x;
    if (idx >= V_ * EPAD) return;
    int tok = idx >> 7;
    int k = idx & (EPAD - 1);
    float v = (k < E_) ? emb[(size_t)tok * E_ + k] : 0.0f;
    __nv_bfloat16 hi, lo; split_bf16(v, hi, lo);
    g_emb_hi[idx] = hi; g_emb_lo[idx] = lo;
}
__global__ void zero_h_kernel() {
    size_t i = (size_t)blockIdx.x * blockDim.x + threadIdx.x;
    if (i < (size_t)B_ * U_) {
        g_h_hi[0][i] = __float2bfloat16(0.0f);
        g_h_lo[0][i] = __float2bfloat16(0.0f);
    }
}

// ---------------- recurrence step: wmma bf16 m16n16k16, 3-MMA split ----------------
// Grid: (U_/NT = 8, B_/MT = 16), 256 threads (8 warps, 4x2 -> 64x64 warp tiles).
__global__ __launch_bounds__(256, 1)
void rnn_step_bf16(const int* __restrict__ inputs, const float* __restrict__ bvec, int t)
{
    extern __shared__ char smem[];
    float* sScr = (float*)(smem + SM_SCR_OFF);
    int*   sIdx = (int*)(smem + SM_IDX_OFF);
    const uint32_t sbase = smem_u32(smem);

    const int tid = threadIdx.x;
    const int wid = tid >> 5;
    const int lane = tid & 31;
    const int warp_m = wid & 3;
    const int warp_n = wid >> 2;
    const int n0 = blockIdx.x * NT;
    const int m0 = blockIdx.y * MT;

    const __nv_bfloat16* __restrict__ hh = g_h_hi[t & 1];
    const __nv_bfloat16* __restrict__ hl = g_h_lo[t & 1];
    __nv_bfloat16* __restrict__ nh = g_h_hi[(t & 1) ^ 1];
    __nv_bfloat16* __restrict__ nl = g_h_lo[(t & 1) ^ 1];

    sIdx[tid] = inputs[(size_t)(m0 + tid) * T_ + t];
    __syncthreads();

    wmma::fragment<wmma::accumulator, 16, 16, 16, float> acc[4][4];
#pragma unroll
    for (int i = 0; i < 4; i++)
#pragma unroll
        for (int j = 0; j < 4; j++) wmma::fill_fragment(acc[i][j], 0.0f);

    auto issue = [&](int c) {
        const int s = c % NSTAGE;
        const uint32_t aHiB = sbase + SM_A_OFF + (uint32_t)(s * A_STAGE_B);
        const uint32_t aLoB = aHiB + A_PLANE_B;
        if (c < 32) {
            const __nv_bfloat16* sh = hh + (size_t)m0 * U_ + c * KC;
            const __nv_bfloat16* sl = hl + (size_t)m0 * U_ + c * KC;
#pragma unroll
            for (int r = 0; r < 4; r++) {
                int idx = r * 256 + tid;
                int row = idx >> 2, sc = idx & 3;
                uint32_t off = (uint32_t)(row * (LDAB * 2) + sc * 16);
                cp_async16(aHiB + off, sh + (size_t)row * U_ + sc * 8);
                cp_async16(aLoB + off, sl + (size_t)row * U_ + sc * 8);
            }
        } else {
            const int kb = (c - 32) * KC;
#pragma unroll
            for (int r = 0; r < 4; r++) {
                int idx = r * 256 + tid;
                int row = idx >> 2, sc = idx & 3;
                uint32_t off = (uint32_t)(row * (LDAB * 2) + sc * 16);
                size_t g = (size_t)sIdx[row] * EPAD + kb + sc * 8;
                cp_async16(aHiB + off, g_emb_hi + g);
                cp_async16(aLoB + off, g_emb_lo + g);
            }
        }
        const uint32_t bHiB = sbase + SM_B_OFF + (uint32_t)(s * B_STAGE_B);
        const uint32_t bLoB = bHiB + B_PLANE_B;
        const __nv_bfloat16* bh = g_Bth + (size_t)n0 * KTOT + c * KC;
        const __nv_bfloat16* bl = g_Btl + (size_t)n0 * KTOT + c * KC;
#pragma unroll
        for (int r = 0; r < 2; r++) {
            int idx = r * 256 + tid;
            int row = idx >> 2, sc = idx & 3;
            uint32_t off = (uint32_t)(row * (LDAB * 2) + sc * 16);
            cp_async16(bHiB + off, bh + (size_t)row * KTOT + sc * 8);
            cp_async16(bLoB + off, bl + (size_t)row * KTOT + sc * 8);
        }
        asm volatile("cp.async.commit_group;" ::: "memory");
    };

    issue(0); issue(1); issue(2);

    for (int c = 0; c < NCHUNK; c++) {
        if (c <= NCHUNK - 3)      asm volatile("cp.async.wait_group 2;" ::: "memory");
        else if (c == NCHUNK - 2) asm volatile("cp.async.wait_group 1;" ::: "memory");
        else                      asm volatile("cp.async.wait_group 0;" ::: "memory");
        __syncthreads();

        const int s = c % NSTAGE;
        const __nv_bfloat16* AsH =
            (const __nv_bfloat16*)(smem + SM_A_OFF + s * A_STAGE_B) + warp_m * 64 * LDAB;
        const __nv_bfloat16* AsL = AsH + A_PLANE_B / 2;
        const __nv_bfloat16* BsH =
            (const __nv_bfloat16*)(smem + SM_B_OFF + s * B_STAGE_B) + warp_n * 64 * LDAB;
        const __nv_bfloat16* BsL = BsH + B_PLANE_B / 2;

#pragma unroll
        for (int k16 = 0; k16 < 2; k16++) {
            wmma::fragment<wmma::matrix_b, 16, 16, 16, __nv_bfloat16, wmma::col_major> bHf[4], bLf[4];
#pragma unroll
            for (int j = 0; j < 4; j++) {
                wmma::load_matrix_sync(bHf[j], BsH + j * 16 * LDAB + k16 * 16, LDAB);
                wmma::load_matrix_sync(bLf[j], BsL + j * 16 * LDAB + k16 * 16, LDAB);
            }
#pragma unroll
            for (int i = 0; i < 4; i++) {
                wmma::fragment<wmma::matrix_a, 16, 16, 16, __nv_bfloat16, wmma::row_major> aHf, aLf;
                wmma::load_matrix_sync(aHf, AsH + i * 16 * LDAB + k16 * 16, LDAB);
                wmma::load_matrix_sync(aLf, AsL + i * 16 * LDAB + k16 * 16, LDAB);
#pragma unroll
                for (int j = 0; j < 4; j++) {
                    wmma::mma_sync(acc[i][j], aHf, bHf[j], acc[i][j]);
                    wmma::mma_sync(acc[i][j], aLf, bHf[j], acc[i][j]);
                    wmma::mma_sync(acc[i][j], aHf, bLf[j], acc[i][j]);
                }
            }
        }
        __syncthreads();
        if (c + NSTAGE < NCHUNK) issue(c + NSTAGE);
    }

    // ---- epilogue: bias + tanh + bf16 hi/lo split + store ----
    float* scr = sScr + wid * (16 * 24);
    const int er = lane >> 1;
    const int ec = (lane & 1) * 8;
#pragma unroll
    for (int mi = 0; mi < 4; mi++) {
#pragma unroll
        for (int ni = 0; ni < 4; ni++) {
            wmma::store_matrix_sync(scr, acc[mi][ni], 24, wmma::mem_row_major);
            __syncwarp();
            int gr = m0 + warp_m * 64 + mi * 16 + er;
            int gc = n0 + warp_n * 64 + ni * 16 + ec;
            float4 v0 = *(float4*)(scr + er * 24 + ec);
            float4 v1 = *(float4*)(scr + er * 24 + ec + 4);
            const float* bb = bvec + gc;
            float vv[8] = { v0.x + bb[0], v0.y + bb[1], v0.z + bb[2], v0.w + bb[3],
                            v1.x + bb[4], v1.y + bb[5], v1.z + bb[6], v1.w + bb[7] };
            __align__(16) __nv_bfloat162 ph[4];
            __align__(16) __nv_bfloat162 pl[4];
#pragma unroll
            for (int e = 0; e < 4; e++) {
                __nv_bfloat16 h0, l0, h1, l1;
                split_bf16(tanhf(vv[2 * e]), h0, l0);
                split_bf16(tanhf(vv[2 * e + 1]), h1, l1);
                ph[e] = __halves2bfloat162(h0, h1);
                pl[e] = __halves2bfloat162(l0, l1);
            }
            size_t o = (size_t)gr * U_ + gc;
            *(uint4*)(nh + o) = *(uint4*)ph;
            *(uint4*)(nl + o) = *(uint4*)pl;
            __syncwarp();
        }
    }
}

// out[row] = h_last[row, :] @ Wo + bo
__global__ void final_proj_kernel(const float* __restrict__ Wo,
                                  const float* __restrict__ bo,
                                  float* __restrict__ out)
{
    const __nv_bfloat16* hh = g_h_hi[0];   // T_=80 even -> final state in buffer 0
    const __nv_bfloat16* hl = g_h_lo[0];
    int row = blockIdx.x;
    int tid = threadIdx.x;     // 128 threads
    float s = 0.0f;
    size_t base = (size_t)row * U_;
#pragma unroll 4
    for (int i = tid; i < U_; i += 128) {
        float hv = __bfloat162float(hh[base + i]) + __bfloat162float(hl[base + i]);
        s += hv * Wo[i];
    }
#pragma unroll
    for (int o = 16; o > 0; o >>= 1) s += __shfl_down_sync(0xffffffffu, s, o);
    __shared__ float red[4];
    if ((tid & 31) == 0) red[tid >> 5] = s;
    __syncthreads();
    if (tid == 0) out[row] = red[0] + red[1] + red[2] + red[3] + bo[0];
}

extern "C" void kernel_launch(void* const* d_in, const int* in_sizes, int n_in,
                              void* d_out, int out_size)
{
    const int*   inputs = (const int*)  d_in[0];
    const float* emb    = (const float*)d_in[1];
    const float* Wx     = (const float*)d_in[2];
    const float* Wh     = (const float*)d_in[3];
    const float* b      = (const float*)d_in[4];
    const float* Wo     = (const float*)d_in[5];
    const float* bo     = (const float*)d_in[6];
    float* out = (float*)d_out;

    cudaFuncSetAttribute(rnn_step_bf16, cudaFuncAttributeMaxDynamicSharedMemorySize,
                         SMEM_TOTAL);

    // Prep: split/transposed/padded bf16 weights + embedding, h0 = 0
    prep_bt_kernel<<<(U_ * KTOT + 255) / 256, 256>>>(Wh, Wx);
    prep_emb_kernel<<<(V_ * EPAD + 255) / 256, 256>>>(emb);
    {
        size_t n = (size_t)B_ * U_;
        zero_h_kernel<<<(int)((n + 255) / 256), 256>>>();
    }

    // 80 recurrence steps (ping-pong hi/lo planes)
    dim3 grid(U_ / NT, B_ / MT);
    for (int t = 0; t < T_; t++) {
        rnn_step_bf16<<<grid, 256, SMEM_TOTAL>>>(inputs, b, t);
    }

    final_proj_kernel<<<B_, 128>>>(Wo, bo, out);
}